// round 2
// baseline (speedup 1.0000x reference)
#include <cuda_runtime.h>

#define NN   50000
#define DIN  128
#define DOUT 64
#define EE   800000
#define TILE 16   // nodes per block in the GEMM kernel

// Scratch for projected features X = BN(normalize(H)) @ W + b   [NN, DOUT]
__device__ float g_X[NN * DOUT];

// ---------------------------------------------------------------------------
// Kernel 0: zero the output (harness poisons it to 0xAA)
// ---------------------------------------------------------------------------
__global__ void zero_out_kernel(float* __restrict__ out, int n4) {
    int i = blockIdx.x * blockDim.x + threadIdx.x;
    if (i < n4) {
        float4 z = make_float4(0.f, 0.f, 0.f, 0.f);
        reinterpret_cast<float4*>(out)[i] = z;
    }
}

// ---------------------------------------------------------------------------
// Kernel 1: fused L2-normalize + BatchNorm(eval) + Linear(128->64) + bias
//   One block handles TILE=16 nodes with 256 threads.
//   smem: W (32KB) + H tile (8KB) + BN consts (1KB) = ~41KB -> 5 CTAs/SM.
// ---------------------------------------------------------------------------
__global__ __launch_bounds__(256) void fused_gemm_kernel(
    const float* __restrict__ H,
    const float* __restrict__ gamma,
    const float* __restrict__ beta,
    const float* __restrict__ mean,
    const float* __restrict__ var,
    const float* __restrict__ W,
    const float* __restrict__ bias)
{
    __shared__ float sW[DIN * DOUT];   // 32 KB
    __shared__ float sH[TILE * DIN];   // 8 KB  (raw H, then in-place BN'd)
    __shared__ float sA[DIN];          // gamma * rsqrt(var+eps)
    __shared__ float sC[DIN];          // beta - mean * sA
    __shared__ float sInv[TILE];       // 1/max(||row||, 1e-12)

    const int tid   = threadIdx.x;
    const int node0 = blockIdx.x * TILE;

    // Stage W into smem (coalesced; W is L2-resident after first wave)
    #pragma unroll 4
    for (int i = tid; i < DIN * DOUT; i += 256) sW[i] = W[i];

    // BN per-feature constants
    if (tid < DIN) {
        float a = gamma[tid] * rsqrtf(var[tid] + 1e-5f);
        sA[tid] = a;
        sC[tid] = beta[tid] - mean[tid] * a;
    }

    // Stage H tile (contiguous 16*128 floats)
    #pragma unroll
    for (int i = tid; i < TILE * DIN; i += 256)
        sH[i] = H[node0 * DIN + i];
    __syncthreads();

    // Row L2 norms: 8 threads per node (warps 0..3 fully active)
    if (tid < TILE * 8) {
        int n = tid >> 3, l = tid & 7;
        float ss = 0.f;
        #pragma unroll
        for (int k = 0; k < 16; k++) {
            float v = sH[n * DIN + l * 16 + k];
            ss += v * v;
        }
        #pragma unroll
        for (int o = 4; o > 0; o >>= 1)
            ss += __shfl_xor_sync(0xffffffffu, ss, o);
        if (l == 0) sInv[n] = 1.0f / fmaxf(sqrtf(ss), 1e-12f);
    }
    __syncthreads();

    // Apply normalize + BN in place
    #pragma unroll
    for (int i = tid; i < TILE * DIN; i += 256) {
        int n = i >> 7, k = i & 127;
        sH[i] = fmaf(sH[i] * sInv[n], sA[k], sC[k]);
    }
    __syncthreads();

    // GEMM: thread owns (node = tid/16, 4 consecutive outputs)
    const int n  = tid >> 4;
    const int j0 = (tid & 15) * 4;
    float4 acc = make_float4(0.f, 0.f, 0.f, 0.f);
    #pragma unroll 8
    for (int k = 0; k < DIN; k++) {
        float  h = sH[n * DIN + k];
        float4 w = *reinterpret_cast<const float4*>(&sW[k * DOUT + j0]);
        acc.x = fmaf(h, w.x, acc.x);
        acc.y = fmaf(h, w.y, acc.y);
        acc.z = fmaf(h, w.z, acc.z);
        acc.w = fmaf(h, w.w, acc.w);
    }
    float4 bb = *reinterpret_cast<const float4*>(&bias[j0]);
    acc.x += bb.x; acc.y += bb.y; acc.z += bb.z; acc.w += bb.w;
    *reinterpret_cast<float4*>(&g_X[(node0 + n) * DOUT + j0]) = acc;
}

// ---------------------------------------------------------------------------
// Kernel 2: edge-parallel SpMM. 16 threads per edge, float4 gather of X,
//   4 scalar atomicAdds into out[row].
// ---------------------------------------------------------------------------
__global__ __launch_bounds__(256) void spmm_kernel(
    const int*   __restrict__ rows,
    const int*   __restrict__ cols,
    const float* __restrict__ vals,
    float*       __restrict__ out)
{
    long long idx = (long long)blockIdx.x * 256 + threadIdx.x; // e*16 + chunk
    int e = (int)(idx >> 4);
    if (e >= EE) return;
    int c = ((int)idx & 15) * 4;

    int   r  = rows[e];
    int   cl = cols[e];
    float v  = vals[e];

    float4 x = *reinterpret_cast<const float4*>(&g_X[cl * DOUT + c]);
    float* o = &out[r * DOUT + c];
    atomicAdd(o + 0, v * x.x);
    atomicAdd(o + 1, v * x.y);
    atomicAdd(o + 2, v * x.z);
    atomicAdd(o + 3, v * x.w);
}

// ---------------------------------------------------------------------------
// Kernel 3: LeakyReLU epilogue
// ---------------------------------------------------------------------------
__global__ void leaky_kernel(float* __restrict__ out, int n4) {
    int i = blockIdx.x * blockDim.x + threadIdx.x;
    if (i < n4) {
        float4 v = reinterpret_cast<float4*>(out)[i];
        v.x = v.x >= 0.f ? v.x : 0.01f * v.x;
        v.y = v.y >= 0.f ? v.y : 0.01f * v.y;
        v.z = v.z >= 0.f ? v.z : 0.01f * v.z;
        v.w = v.w >= 0.f ? v.w : 0.01f * v.w;
        reinterpret_cast<float4*>(out)[i] = v;
    }
}

// ---------------------------------------------------------------------------
extern "C" void kernel_launch(void* const* d_in, const int* in_sizes, int n_in,
                              void* d_out, int out_size) {
    const float* H     = (const float*)d_in[0];
    const int*   rows  = (const int*)  d_in[1];
    const int*   cols  = (const int*)  d_in[2];
    const float* vals  = (const float*)d_in[3];
    const float* gamma = (const float*)d_in[4];
    const float* beta  = (const float*)d_in[5];
    const float* rmean = (const float*)d_in[6];
    const float* rvar  = (const float*)d_in[7];
    const float* W     = (const float*)d_in[8];
    const float* b     = (const float*)d_in[9];
    float* out = (float*)d_out;

    const int n4 = NN * DOUT / 4;                 // 800000
    zero_out_kernel<<<(n4 + 255) / 256, 256>>>(out, n4);

    fused_gemm_kernel<<<NN / TILE, 256>>>(H, gamma, beta, rmean, rvar, W, b);

    const long long work = (long long)EE * 16;    // 12.8M threads
    spmm_kernel<<<(unsigned)((work + 255) / 256), 256>>>(rows, cols, vals, out);

    leaky_kernel<<<(n4 + 255) / 256, 256>>>(out, n4);
}

// round 4
// speedup vs baseline: 1.2435x; 1.2435x over previous
#include <cuda_runtime.h>

#define NN    50000
#define DIN   128
#define DOUT  64
#define EE    800000
#define GTILE 64          // nodes per block in GEMM
#define SHPAD 132         // padded row stride for sH (132%4==0, breaks bank conflicts)

// ---------------------------------------------------------------------------
// Device scratch (allocation-free rule: __device__ globals)
// ---------------------------------------------------------------------------
__device__ float g_X[NN * DOUT];       // projected features
__device__ int   g_cnt[NN];            // degree counters / scatter cursors
__device__ int   g_rowptr[NN + 1];     // CSR row offsets
__device__ int   g_ecol[EE];           // CSR cols
__device__ float g_eval[EE];           // CSR vals

// ---------------------------------------------------------------------------
// CSR build step 1: zero counters
// ---------------------------------------------------------------------------
__global__ void zero_cnt_kernel() {
    int i = blockIdx.x * blockDim.x + threadIdx.x;
    if (i < NN) g_cnt[i] = 0;
}

// CSR build step 2: histogram of rows
__global__ void hist_kernel(const int* __restrict__ rows) {
    int e = blockIdx.x * blockDim.x + threadIdx.x;
    if (e < EE) atomicAdd(&g_cnt[rows[e]], 1);
}

// CSR build step 3: exclusive scan of degrees (single block, 1024 threads)
__global__ __launch_bounds__(1024) void scan_kernel() {
    __shared__ int part[1024];
    const int C = (NN + 1023) / 1024;          // 49 elements per thread
    int t = threadIdx.x;
    int base = t * C;

    int sum = 0;
    for (int i = 0; i < C; i++) {
        int idx = base + i;
        if (idx < NN) sum += g_cnt[idx];
    }
    part[t] = sum;
    __syncthreads();

    // Hillis-Steele inclusive scan over 1024 partials
    for (int off = 1; off < 1024; off <<= 1) {
        int v = (t >= off) ? part[t - off] : 0;
        __syncthreads();
        part[t] += v;
        __syncthreads();
    }

    int running = (t == 0) ? 0 : part[t - 1];  // exclusive base for this chunk
    for (int i = 0; i < C; i++) {
        int idx = base + i;
        if (idx < NN) {
            int c = g_cnt[idx];
            g_rowptr[idx] = running;
            g_cnt[idx]    = running;           // becomes scatter cursor
            running += c;
        }
    }
    if (t == 1023) g_rowptr[NN] = running;     // == EE
}

// CSR build step 4: scatter edges into CSR order
__global__ void scatter_kernel(const int* __restrict__ rows,
                               const int* __restrict__ cols,
                               const float* __restrict__ vals) {
    int e = blockIdx.x * blockDim.x + threadIdx.x;
    if (e < EE) {
        int pos = atomicAdd(&g_cnt[rows[e]], 1);
        g_ecol[pos] = cols[e];
        g_eval[pos] = vals[e];
    }
}

// ---------------------------------------------------------------------------
// Fused L2-normalize + BN(eval) + Linear(128->64)+bias -> g_X
//   64 nodes / block, 256 threads, each thread computes 4 nodes x 4 cols.
//   smem ~66 KB -> 3 CTAs/SM.
// ---------------------------------------------------------------------------
__global__ __launch_bounds__(256) void fused_gemm_kernel(
    const float* __restrict__ H,
    const float* __restrict__ gamma,
    const float* __restrict__ beta,
    const float* __restrict__ mean,
    const float* __restrict__ var,
    const float* __restrict__ W,
    const float* __restrict__ bias)
{
    __shared__ float sW[DIN * DOUT];        // 32 KB
    __shared__ float sH[GTILE * SHPAD];     // 33.8 KB, padded stride
    __shared__ float sA[DIN];
    __shared__ float sC[DIN];
    __shared__ float sInv[GTILE];

    const int tid   = threadIdx.x;
    const int node0 = blockIdx.x * GTILE;
    const int nvalid = min(GTILE, NN - node0);

    // Stage W (coalesced float4)
    #pragma unroll 4
    for (int i = tid; i < DIN * DOUT / 4; i += 256)
        reinterpret_cast<float4*>(sW)[i] =
            reinterpret_cast<const float4*>(W)[i];

    if (tid < DIN) {
        float a = gamma[tid] * rsqrtf(var[tid] + 1e-5f);
        sA[tid] = a;
        sC[tid] = beta[tid] - mean[tid] * a;
    }

    // Stage H tile: float4 per lane, one row per warp-instruction
    #pragma unroll
    for (int i4 = tid; i4 < GTILE * (DIN / 4); i4 += 256) {
        int r = i4 >> 5;           // row within tile
        int c = (i4 & 31) * 4;     // col
        float4 v = (r < nvalid)
            ? reinterpret_cast<const float4*>(H)[(node0 + r) * (DIN / 4) + (c >> 2)]
            : make_float4(1.f, 0.f, 0.f, 0.f);
        *reinterpret_cast<float4*>(&sH[r * SHPAD + c]) = v;
    }
    __syncthreads();

    // Row L2 norms: 4 threads per row, 32 elems each
    {
        int r = tid >> 2, l = tid & 3;
        float ss = 0.f;
        #pragma unroll
        for (int i = 0; i < 8; i++) {
            float4 v = *reinterpret_cast<float4*>(&sH[r * SHPAD + l * 32 + i * 4]);
            ss += v.x * v.x + v.y * v.y + v.z * v.z + v.w * v.w;
        }
        ss += __shfl_xor_sync(0xffffffffu, ss, 1);
        ss += __shfl_xor_sync(0xffffffffu, ss, 2);
        if (l == 0) sInv[r] = 1.0f / fmaxf(sqrtf(ss), 1e-12f);
    }
    __syncthreads();

    // Apply normalize + BN in place (float4)
    #pragma unroll
    for (int i4 = tid; i4 < GTILE * (DIN / 4); i4 += 256) {
        int r = i4 >> 5;
        int c = (i4 & 31) * 4;
        float inv = sInv[r];
        float4 h = *reinterpret_cast<float4*>(&sH[r * SHPAD + c]);
        float4 a = *reinterpret_cast<float4*>(&sA[c]);
        float4 cc = *reinterpret_cast<float4*>(&sC[c]);
        h.x = fmaf(h.x * inv, a.x, cc.x);
        h.y = fmaf(h.y * inv, a.y, cc.y);
        h.z = fmaf(h.z * inv, a.z, cc.z);
        h.w = fmaf(h.w * inv, a.w, cc.w);
        *reinterpret_cast<float4*>(&sH[r * SHPAD + c]) = h;
    }
    __syncthreads();

    // GEMM: thread = (node group ng: 4 nodes, col group jg: 4 cols)
    const int jg = tid & 15;         // 16 col groups * 4 = 64 cols
    const int ng = tid >> 4;         // 16 node groups * 4 = 64 nodes
    const int n0 = ng * 4;
    const int j0 = jg * 4;

    float4 acc0 = make_float4(0.f, 0.f, 0.f, 0.f);
    float4 acc1 = make_float4(0.f, 0.f, 0.f, 0.f);
    float4 acc2 = make_float4(0.f, 0.f, 0.f, 0.f);
    float4 acc3 = make_float4(0.f, 0.f, 0.f, 0.f);

    #pragma unroll 8
    for (int k = 0; k < DIN; k++) {
        float4 w = *reinterpret_cast<float4*>(&sW[k * DOUT + j0]);
        float h0 = sH[(n0 + 0) * SHPAD + k];
        float h1 = sH[(n0 + 1) * SHPAD + k];
        float h2 = sH[(n0 + 2) * SHPAD + k];
        float h3 = sH[(n0 + 3) * SHPAD + k];
        acc0.x = fmaf(h0, w.x, acc0.x); acc0.y = fmaf(h0, w.y, acc0.y);
        acc0.z = fmaf(h0, w.z, acc0.z); acc0.w = fmaf(h0, w.w, acc0.w);
        acc1.x = fmaf(h1, w.x, acc1.x); acc1.y = fmaf(h1, w.y, acc1.y);
        acc1.z = fmaf(h1, w.z, acc1.z); acc1.w = fmaf(h1, w.w, acc1.w);
        acc2.x = fmaf(h2, w.x, acc2.x); acc2.y = fmaf(h2, w.y, acc2.y);
        acc2.z = fmaf(h2, w.z, acc2.z); acc2.w = fmaf(h2, w.w, acc2.w);
        acc3.x = fmaf(h3, w.x, acc3.x); acc3.y = fmaf(h3, w.y, acc3.y);
        acc3.z = fmaf(h3, w.z, acc3.z); acc3.w = fmaf(h3, w.w, acc3.w);
    }

    float4 bb = *reinterpret_cast<const float4*>(&bias[j0]);
    acc0.x += bb.x; acc0.y += bb.y; acc0.z += bb.z; acc0.w += bb.w;
    acc1.x += bb.x; acc1.y += bb.y; acc1.z += bb.z; acc1.w += bb.w;
    acc2.x += bb.x; acc2.y += bb.y; acc2.z += bb.z; acc2.w += bb.w;
    acc3.x += bb.x; acc3.y += bb.y; acc3.z += bb.z; acc3.w += bb.w;

    if (n0 + 0 < nvalid) *reinterpret_cast<float4*>(&g_X[(node0 + n0 + 0) * DOUT + j0]) = acc0;
    if (n0 + 1 < nvalid) *reinterpret_cast<float4*>(&g_X[(node0 + n0 + 1) * DOUT + j0]) = acc1;
    if (n0 + 2 < nvalid) *reinterpret_cast<float4*>(&g_X[(node0 + n0 + 2) * DOUT + j0]) = acc2;
    if (n0 + 3 < nvalid) *reinterpret_cast<float4*>(&g_X[(node0 + n0 + 3) * DOUT + j0]) = acc3;
}

// ---------------------------------------------------------------------------
// Row-parallel SpMM + fused LeakyReLU. 8 threads per row, each owns 8 cols.
// No atomics: each row's edges are contiguous in CSR; output written once.
// ---------------------------------------------------------------------------
__global__ __launch_bounds__(256) void spmm_leaky_kernel(float* __restrict__ out)
{
    int gid  = blockIdx.x * 256 + threadIdx.x;
    int row  = gid >> 3;
    if (row >= NN) return;
    int lane = gid & 7;
    int c0   = lane * 8;

    int s = g_rowptr[row];
    int e = g_rowptr[row + 1];

    float4 a0 = make_float4(0.f, 0.f, 0.f, 0.f);
    float4 a1 = make_float4(0.f, 0.f, 0.f, 0.f);

    for (int p = s; p < e; ++p) {
        int   col = g_ecol[p];
        float v   = g_eval[p];
        const float4* xp = reinterpret_cast<const float4*>(&g_X[col * DOUT + c0]);
        float4 x0 = xp[0];
        float4 x1 = xp[1];
        a0.x = fmaf(v, x0.x, a0.x); a0.y = fmaf(v, x0.y, a0.y);
        a0.z = fmaf(v, x0.z, a0.z); a0.w = fmaf(v, x0.w, a0.w);
        a1.x = fmaf(v, x1.x, a1.x); a1.y = fmaf(v, x1.y, a1.y);
        a1.z = fmaf(v, x1.z, a1.z); a1.w = fmaf(v, x1.w, a1.w);
    }

    // LeakyReLU
    a0.x = a0.x >= 0.f ? a0.x : 0.01f * a0.x;
    a0.y = a0.y >= 0.f ? a0.y : 0.01f * a0.y;
    a0.z = a0.z >= 0.f ? a0.z : 0.01f * a0.z;
    a0.w = a0.w >= 0.f ? a0.w : 0.01f * a0.w;
    a1.x = a1.x >= 0.f ? a1.x : 0.01f * a1.x;
    a1.y = a1.y >= 0.f ? a1.y : 0.01f * a1.y;
    a1.z = a1.z >= 0.f ? a1.z : 0.01f * a1.z;
    a1.w = a1.w >= 0.f ? a1.w : 0.01f * a1.w;

    float4* op = reinterpret_cast<float4*>(&out[row * DOUT + c0]);
    op[0] = a0;
    op[1] = a1;
}

// ---------------------------------------------------------------------------
extern "C" void kernel_launch(void* const* d_in, const int* in_sizes, int n_in,
                              void* d_out, int out_size) {
    const float* H     = (const float*)d_in[0];
    const int*   rows  = (const int*)  d_in[1];
    const int*   cols  = (const int*)  d_in[2];
    const float* vals  = (const float*)d_in[3];
    const float* gamma = (const float*)d_in[4];
    const float* beta  = (const float*)d_in[5];
    const float* rmean = (const float*)d_in[6];
    const float* rvar  = (const float*)d_in[7];
    const float* W     = (const float*)d_in[8];
    const float* b     = (const float*)d_in[9];
    float* out = (float*)d_out;

    // CSR build
    zero_cnt_kernel<<<(NN + 255) / 256, 256>>>();
    hist_kernel<<<(EE + 255) / 256, 256>>>(rows);
    scan_kernel<<<1, 1024>>>();
    scatter_kernel<<<(EE + 255) / 256, 256>>>(rows, cols, vals);

    // Dense part
    fused_gemm_kernel<<<(NN + GTILE - 1) / GTILE, 256>>>(H, gamma, beta,
                                                         rmean, rvar, W, b);

    // Sparse aggregation + activation
    spmm_leaky_kernel<<<(NN * 8 + 255) / 256, 256>>>(out);
}

// round 5
// speedup vs baseline: 2.4142x; 1.9414x over previous
#include <cuda_runtime.h>

#define NN    50000
#define DIN   128
#define DOUT  64
#define EE    800000
#define GTILE 64          // nodes per GEMM block
#define SHPAD 132         // padded sH row stride (breaks bank conflicts)
#define NB1   49          // scan1 blocks (49*1024 >= NN)

// ---------------------------------------------------------------------------
// Device scratch
// ---------------------------------------------------------------------------
__device__ float  g_X[NN * DOUT];     // projected features
__device__ int    g_cnt[NN];          // degree counters -> scatter cursors
__device__ int    g_rowptr[NN + 1];   // CSR row offsets
__device__ int    g_scan[NN];         // block-local exclusive scan
__device__ int    g_bsum[NB1];        // per-block totals
__device__ int    g_boff[NB1];        // per-block exclusive offsets
__device__ float2 g_edge[EE];         // CSR (col as int bits, val)

// ---------------------------------------------------------------------------
// CSR build
// ---------------------------------------------------------------------------
__global__ void zero_cnt_kernel() {
    int i = blockIdx.x * blockDim.x + threadIdx.x;
    if (i < NN) g_cnt[i] = 0;
}

__global__ void hist_kernel(const int* __restrict__ rows) {
    int e = blockIdx.x * blockDim.x + threadIdx.x;
    if (e < EE) atomicAdd(&g_cnt[rows[e]], 1);
}

// scan1: per-block exclusive scan of 1024 degrees + block total
__global__ __launch_bounds__(1024) void scan1_kernel() {
    __shared__ int wsum[32];
    int tid  = threadIdx.x;
    int i    = blockIdx.x * 1024 + tid;
    int lane = tid & 31, warp = tid >> 5;

    int orig = (i < NN) ? g_cnt[i] : 0;
    int v = orig;
    #pragma unroll
    for (int o = 1; o < 32; o <<= 1) {
        int n = __shfl_up_sync(0xffffffffu, v, o);
        if (lane >= o) v += n;
    }
    if (lane == 31) wsum[warp] = v;
    __syncthreads();
    if (warp == 0) {
        int s = wsum[lane];
        #pragma unroll
        for (int o = 1; o < 32; o <<= 1) {
            int n = __shfl_up_sync(0xffffffffu, s, o);
            if (lane >= o) s += n;
        }
        wsum[lane] = s;
    }
    __syncthreads();
    int base = (warp > 0) ? wsum[warp - 1] : 0;
    if (i < NN) g_scan[i] = base + v - orig;
    if (tid == 1023) g_bsum[blockIdx.x] = wsum[31];
}

// scan2: exclusive scan of NB1=49 block totals (single warp, 2 per lane)
__global__ void scan2_kernel() {
    int t = threadIdx.x;  // 32 threads
    int a = (2 * t     < NB1) ? g_bsum[2 * t]     : 0;
    int b = (2 * t + 1 < NB1) ? g_bsum[2 * t + 1] : 0;
    int s = a + b;
    int incl = s;
    #pragma unroll
    for (int o = 1; o < 32; o <<= 1) {
        int n = __shfl_up_sync(0xffffffffu, incl, o);
        if (t >= o) incl += n;
    }
    int excl = incl - s;
    if (2 * t     < NB1) g_boff[2 * t]     = excl;
    if (2 * t + 1 < NB1) g_boff[2 * t + 1] = excl + a;
}

// scan3: finalize rowptr + seed scatter cursors
__global__ void scan3_kernel() {
    int i = blockIdx.x * blockDim.x + threadIdx.x;
    if (i < NN) {
        int r = g_scan[i] + g_boff[i >> 10];
        g_rowptr[i] = r;
        g_cnt[i]    = r;
    }
    if (i == 0) g_rowptr[NN] = EE;
}

// scatter: one 8B packed store per edge
__global__ void scatter_kernel(const int* __restrict__ rows,
                               const int* __restrict__ cols,
                               const float* __restrict__ vals) {
    int e = blockIdx.x * blockDim.x + threadIdx.x;
    if (e < EE) {
        int pos = atomicAdd(&g_cnt[rows[e]], 1);
        g_edge[pos] = make_float2(__int_as_float(cols[e]), vals[e]);
    }
}

// ---------------------------------------------------------------------------
// Fused L2-normalize + BN(eval) + Linear(128->64)+bias -> g_X
//   64 nodes / block, 128 threads, each thread: 8 nodes x 4 cols.
//   smem ~66 KB -> 3 CTAs/SM. 1.5 B LDS per FMA -> FFMA-pipe bound.
// ---------------------------------------------------------------------------
__global__ __launch_bounds__(128) void fused_gemm_kernel(
    const float* __restrict__ H,
    const float* __restrict__ gamma,
    const float* __restrict__ beta,
    const float* __restrict__ mean,
    const float* __restrict__ var,
    const float* __restrict__ W,
    const float* __restrict__ bias)
{
    __shared__ float sW[DIN * DOUT];        // 32 KB
    __shared__ float sH[GTILE * SHPAD];     // 33.8 KB
    __shared__ float sA[DIN];
    __shared__ float sC[DIN];
    __shared__ float sInv[GTILE];

    const int tid    = threadIdx.x;
    const int node0  = blockIdx.x * GTILE;
    const int nvalid = min(GTILE, NN - node0);

    // Stage W (float4, coalesced)
    #pragma unroll
    for (int i = tid; i < DIN * DOUT / 4; i += 128)
        reinterpret_cast<float4*>(sW)[i] =
            reinterpret_cast<const float4*>(W)[i];

    // BN per-feature constants (all 128 threads cover DIN)
    {
        float a = gamma[tid] * rsqrtf(var[tid] + 1e-5f);
        sA[tid] = a;
        sC[tid] = beta[tid] - mean[tid] * a;
    }

    // Stage H tile
    #pragma unroll
    for (int i4 = tid; i4 < GTILE * (DIN / 4); i4 += 128) {
        int r = i4 >> 5;
        int c = (i4 & 31) * 4;
        float4 v = (r < nvalid)
            ? reinterpret_cast<const float4*>(H)[(node0 + r) * (DIN / 4) + (c >> 2)]
            : make_float4(1.f, 0.f, 0.f, 0.f);
        *reinterpret_cast<float4*>(&sH[r * SHPAD + c]) = v;
    }
    __syncthreads();

    // Row L2 norms: 2 threads per row, 64 elems each
    {
        int r = tid >> 1, l = tid & 1;
        float ss = 0.f;
        #pragma unroll
        for (int i = 0; i < 16; i++) {
            float4 v = *reinterpret_cast<float4*>(&sH[r * SHPAD + l * 64 + i * 4]);
            ss += v.x * v.x + v.y * v.y + v.z * v.z + v.w * v.w;
        }
        ss += __shfl_xor_sync(0xffffffffu, ss, 1);
        if (l == 0) sInv[r] = 1.0f / fmaxf(sqrtf(ss), 1e-12f);
    }
    __syncthreads();

    // normalize + BN in place
    #pragma unroll
    for (int i4 = tid; i4 < GTILE * (DIN / 4); i4 += 128) {
        int r = i4 >> 5;
        int c = (i4 & 31) * 4;
        float inv = sInv[r];
        float4 h  = *reinterpret_cast<float4*>(&sH[r * SHPAD + c]);
        float4 a  = *reinterpret_cast<float4*>(&sA[c]);
        float4 cc = *reinterpret_cast<float4*>(&sC[c]);
        h.x = fmaf(h.x * inv, a.x, cc.x);
        h.y = fmaf(h.y * inv, a.y, cc.y);
        h.z = fmaf(h.z * inv, a.z, cc.z);
        h.w = fmaf(h.w * inv, a.w, cc.w);
        *reinterpret_cast<float4*>(&sH[r * SHPAD + c]) = h;
    }
    __syncthreads();

    // GEMM: thread = (8 nodes, 4 cols)
    const int jg = tid & 15;          // 16 col groups * 4 = 64 cols
    const int ng = tid >> 4;          // 8 node groups * 8 = 64 nodes
    const int n0 = ng * 8;
    const int j0 = jg * 4;

    float4 acc[8];
    #pragma unroll
    for (int i = 0; i < 8; i++) acc[i] = make_float4(0.f, 0.f, 0.f, 0.f);

    #pragma unroll 4
    for (int k = 0; k < DIN; k++) {
        float4 w = *reinterpret_cast<float4*>(&sW[k * DOUT + j0]);
        #pragma unroll
        for (int i = 0; i < 8; i++) {
            float h = sH[(n0 + i) * SHPAD + k];
            acc[i].x = fmaf(h, w.x, acc[i].x);
            acc[i].y = fmaf(h, w.y, acc[i].y);
            acc[i].z = fmaf(h, w.z, acc[i].z);
            acc[i].w = fmaf(h, w.w, acc[i].w);
        }
    }

    float4 bb = *reinterpret_cast<const float4*>(&bias[j0]);
    #pragma unroll
    for (int i = 0; i < 8; i++) {
        if (n0 + i < nvalid) {
            float4 a = acc[i];
            a.x += bb.x; a.y += bb.y; a.z += bb.z; a.w += bb.w;
            *reinterpret_cast<float4*>(&g_X[(node0 + n0 + i) * DOUT + j0]) = a;
        }
    }
}

// ---------------------------------------------------------------------------
// Row-parallel SpMM + LeakyReLU: 16 threads per row, float4 per lane.
// Each edge record is one broadcast 8B load; X row gather is 256B coalesced.
// ---------------------------------------------------------------------------
__global__ __launch_bounds__(256) void spmm_leaky_kernel(float* __restrict__ out)
{
    int gid  = blockIdx.x * 256 + threadIdx.x;
    int row  = gid >> 4;
    if (row >= NN) return;
    int lane = gid & 15;
    int c0   = lane * 4;

    int s = g_rowptr[row];
    int e = g_rowptr[row + 1];

    float4 a = make_float4(0.f, 0.f, 0.f, 0.f);

    for (int p = s; p < e; ++p) {
        float2 ev = g_edge[p];
        int   col = __float_as_int(ev.x);
        float v   = ev.y;
        float4 x  = *reinterpret_cast<const float4*>(&g_X[col * DOUT + c0]);
        a.x = fmaf(v, x.x, a.x);
        a.y = fmaf(v, x.y, a.y);
        a.z = fmaf(v, x.z, a.z);
        a.w = fmaf(v, x.w, a.w);
    }

    a.x = a.x >= 0.f ? a.x : 0.01f * a.x;
    a.y = a.y >= 0.f ? a.y : 0.01f * a.y;
    a.z = a.z >= 0.f ? a.z : 0.01f * a.z;
    a.w = a.w >= 0.f ? a.w : 0.01f * a.w;

    *reinterpret_cast<float4*>(&out[row * DOUT + c0]) = a;
}

// ---------------------------------------------------------------------------
extern "C" void kernel_launch(void* const* d_in, const int* in_sizes, int n_in,
                              void* d_out, int out_size) {
    const float* H     = (const float*)d_in[0];
    const int*   rows  = (const int*)  d_in[1];
    const int*   cols  = (const int*)  d_in[2];
    const float* vals  = (const float*)d_in[3];
    const float* gamma = (const float*)d_in[4];
    const float* beta  = (const float*)d_in[5];
    const float* rmean = (const float*)d_in[6];
    const float* rvar  = (const float*)d_in[7];
    const float* W     = (const float*)d_in[8];
    const float* b     = (const float*)d_in[9];
    float* out = (float*)d_out;

    // CSR build (fully parallel scan)
    zero_cnt_kernel<<<(NN + 255) / 256, 256>>>();
    hist_kernel<<<(EE + 255) / 256, 256>>>(rows);
    scan1_kernel<<<NB1, 1024>>>();
    scan2_kernel<<<1, 32>>>();
    scan3_kernel<<<(NN + 255) / 256, 256>>>();
    scatter_kernel<<<(EE + 255) / 256, 256>>>(rows, cols, vals);

    // Dense part
    fused_gemm_kernel<<<(NN + GTILE - 1) / GTILE, 128>>>(H, gamma, beta,
                                                         rmean, rvar, W, b);

    // Sparse aggregation + activation
    spmm_leaky_kernel<<<(NN * 16 + 255) / 256, 256>>>(out);
}